// round 8
// baseline (speedup 1.0000x reference)
#include <cuda_runtime.h>

// ---------------- problem constants ----------------
#define NPART   65536
#define DDIM    8
#define HID     64
#define WIDTH   128
#define TT      8
#define NSUB    4
#define NSEG    7
#define NSLOT   63            // 7 segments * 9 time slots
#define SLOT_F  4612          // 4 header floats + 128 rows * 36 floats
#define POUT    3200          // 3*WIDTH*DDIM + WIDTH
#define ZT_ELEMS (TT*NPART*DDIM)

// Coefficient slots: per slot: [0..1]=(-Csum,-Csum), [2..3]=pad,
// then per row i (36 floats): W dup x8 (16), U' dup x8 (16), (B,B,c,c) (4).
__device__ __align__(16) float g_slots[(size_t)NSLOT * SLOT_F];

typedef unsigned long long u64;

// ---------------- f32x2 helpers ----------------
__device__ __forceinline__ u64 pk(float x, float y) {
    u64 r; asm("mov.b64 %0, {%1, %2};" : "=l"(r) : "f"(x), "f"(y)); return r;
}
__device__ __forceinline__ void upk(float& x, float& y, u64 v) {
    asm("mov.b64 {%0, %1}, %2;" : "=f"(x), "=f"(y) : "l"(v));
}
__device__ __forceinline__ u64 f2(u64 a, u64 b, u64 c) {
    u64 d; asm("fma.rn.f32x2 %0, %1, %2, %3;" : "=l"(d) : "l"(a), "l"(b), "l"(c)); return d;
}
__device__ __forceinline__ u64 m2(u64 a, u64 b) {
    u64 d; asm("mul.rn.f32x2 %0, %1, %2;" : "=l"(d) : "l"(a), "l"(b)); return d;
}
__device__ __forceinline__ u64 a2(u64 a, u64 b) {
    u64 d; asm("add.rn.f32x2 %0, %1, %2;" : "=l"(d) : "l"(a), "l"(b)); return d;
}
__device__ __forceinline__ float tnh(float x) {
    float r; asm("tanh.approx.f32 %0, %1;" : "=f"(r) : "f"(x)); return r;
}
__device__ __forceinline__ void lds2(u64& a, u64& b, unsigned addr) {
    asm volatile("ld.shared.v2.b64 {%0, %1}, [%2];" : "=l"(a), "=l"(b) : "r"(addr));
}
__device__ __forceinline__ u64 lds1(unsigned addr) {
    u64 a; asm volatile("ld.shared.b64 %0, [%1];" : "=l"(a) : "r"(addr)); return a;
}

// ---------------- hypernet precompute: 63 slots ----------------
__global__ void hyper_kernel(const float* __restrict__ ts,
                             const float* __restrict__ w1, const float* __restrict__ b1,
                             const float* __restrict__ w2, const float* __restrict__ b2,
                             const float* __restrict__ w3, const float* __restrict__ b3)
{
    __shared__ float h1s[HID];
    __shared__ float h2s[HID];
    __shared__ float ps[POUT];
    __shared__ float csh[WIDTH];

    int s = blockIdx.x;
    int j = s / 9, m = s % 9;
    float t0 = ts[j], t1 = ts[j + 1];
    float t = t0 + (float)m * (t1 - t0) * 0.125f;   // t0 + m*dt/2, dt=(t1-t0)/4
    int tid = threadIdx.x;                           // 128 threads

    if (tid < HID) h1s[tid] = tanhf(w1[tid] * t + b1[tid]);
    __syncthreads();
    if (tid < HID) {
        float acc = b2[tid];
        const float* wr = w2 + tid * HID;
        #pragma unroll 8
        for (int k = 0; k < HID; k++) acc = fmaf(wr[k], h1s[k], acc);
        h2s[tid] = tanhf(acc);
    }
    __syncthreads();
    for (int o = tid; o < POUT; o += 128) {
        float acc = b3[o];
        const float4* wr = (const float4*)(w3 + (size_t)o * HID);
        #pragma unroll
        for (int k = 0; k < HID / 4; k++) {
            float4 v = wr[k];
            acc = fmaf(v.x, h2s[4 * k + 0], acc);
            acc = fmaf(v.y, h2s[4 * k + 1], acc);
            acc = fmaf(v.z, h2s[4 * k + 2], acc);
            acc = fmaf(v.w, h2s[4 * k + 3], acc);
        }
        ps[o] = acc;
    }
    __syncthreads();

    float* slot = g_slots + (size_t)s * SLOT_F;
    {
        int i = tid;                                 // 128 rows, one per thread
        float c = 0.f;
        float* row = slot + 4 + i * 36;
        float B = ps[3 * WIDTH * DDIM + i];
        #pragma unroll
        for (int d = 0; d < DDIM; d++) {
            float w = ps[i * 8 + d];
            float u = ps[1024 + i * 8 + d];
            float g = ps[2048 + i * 8 + d];
            float sg = 1.f / (1.f + expf(-g));
            u = u * sg * (1.0f / (float)WIDTH);      // pre-scale U by 1/WIDTH
            row[2 * d + 0] = w;  row[2 * d + 1] = w;
            row[16 + 2 * d + 0] = u;  row[16 + 2 * d + 1] = u;
            c = fmaf(w, u, c);                       // c already includes 1/WIDTH
        }
        row[32] = B; row[33] = B; row[34] = c; row[35] = c;
        csh[i] = c;
    }
    __syncthreads();
    if (tid == 0) {
        float cs = 0.f;
        for (int i = 0; i < WIDTH; i++) cs += csh[i];
        slot[0] = -cs; slot[1] = -cs; slot[2] = 0.f; slot[3] = 0.f;  // -Csum
    }
}

// ---------------- RHS eval: TWO pairs of particles packed f32x2 ----------------
// zs[0..7] = pair A dims, zs[8..15] = pair B dims. Same for dz. dl[2].
__device__ __forceinline__ void rhs_eval2(unsigned sb, const u64 zs[16], u64 dz[16], u64 dl[2])
{
    u64 Sa = 0ull, Sb = 0ull;
    #pragma unroll
    for (int d = 0; d < 16; d++) dz[d] = 0ull;
    unsigned a = sb + 16;
    #pragma unroll 2
    for (int i = 0; i < WIDTH; i++) {
        u64 q0, q1, q2, q3, q4, q5, q6, q7, Bd, Cd;
        lds2(Bd, Cd, a + 128);
        lds2(q0, q1, a);      lds2(q2, q3, a + 16);
        lds2(q4, q5, a + 32); lds2(q6, q7, a + 48);
        // pair A preactivation
        u64 ea = f2(q0, zs[0], Bd);
        u64 oa = m2(q1, zs[1]);
        ea = f2(q2, zs[2], ea);  oa = f2(q3, zs[3], oa);
        ea = f2(q4, zs[4], ea);  oa = f2(q5, zs[5], oa);
        ea = f2(q6, zs[6], ea);  oa = f2(q7, zs[7], oa);
        // pair B preactivation (reuses same coefficient regs)
        u64 eb = f2(q0, zs[8],  Bd);
        u64 ob = m2(q1, zs[9]);
        eb = f2(q2, zs[10], eb); ob = f2(q3, zs[11], ob);
        eb = f2(q4, zs[12], eb); ob = f2(q5, zs[13], ob);
        eb = f2(q6, zs[14], eb); ob = f2(q7, zs[15], ob);
        u64 pa = a2(ea, oa);
        u64 pb = a2(eb, ob);
        float ax, ay, bx, by;
        upk(ax, ay, pa); upk(bx, by, pb);
        u64 ha = pk(tnh(ax), tnh(ay));
        u64 hb = pk(tnh(bx), tnh(by));
        Sa = f2(m2(ha, ha), Cd, Sa);           // S = sum h^2 * c
        Sb = f2(m2(hb, hb), Cd, Sb);
        lds2(q0, q1, a + 64);  lds2(q2, q3, a + 80);
        lds2(q4, q5, a + 96);  lds2(q6, q7, a + 112);
        dz[0]  = f2(ha, q0, dz[0]);   dz[1]  = f2(ha, q1, dz[1]);
        dz[2]  = f2(ha, q2, dz[2]);   dz[3]  = f2(ha, q3, dz[3]);
        dz[4]  = f2(ha, q4, dz[4]);   dz[5]  = f2(ha, q5, dz[5]);
        dz[6]  = f2(ha, q6, dz[6]);   dz[7]  = f2(ha, q7, dz[7]);
        dz[8]  = f2(hb, q0, dz[8]);   dz[9]  = f2(hb, q1, dz[9]);
        dz[10] = f2(hb, q2, dz[10]);  dz[11] = f2(hb, q3, dz[11]);
        dz[12] = f2(hb, q4, dz[12]);  dz[13] = f2(hb, q5, dz[13]);
        dz[14] = f2(hb, q6, dz[14]);  dz[15] = f2(hb, q7, dz[15]);
        a += 144;
    }
    u64 nCs = lds1(sb);                        // (-Csum, -Csum)
    dl[0] = a2(Sa, nCs);                       // dlogp/dt = S - Csum = -trace
    dl[1] = a2(Sb, nCs);
}

__device__ __forceinline__ void stage_slot(float4* s4, const float4* g4, int tid)
{
    __syncthreads();
    #pragma unroll
    for (int k = 0; k < 9; k++) s4[tid + k * 128] = g4[tid + k * 128];
    if (tid == 0) s4[1152] = g4[1152];
    __syncthreads();
}

// ---------------- main integration kernel ----------------
// 128 CTAs x 128 threads, 2 particle-pairs (4 particles) per thread -> ONE wave.
__global__ void __launch_bounds__(128) cnf_main(const float* __restrict__ ts,
                                                const float* __restrict__ z0,
                                                const float* __restrict__ lp0,
                                                float* __restrict__ out)
{
    __shared__ __align__(16) float sco[SLOT_F];
    unsigned sb = (unsigned)__cvta_generic_to_shared(sco);
    float4* s4 = (float4*)sco;
    int tid = threadIdx.x;
    int PA = blockIdx.x * 256 + tid;           // pair A index
    int PB = PA + 128;                         // pair B index

    u64 zz[16], ll[2];
    // load both pairs' initial state and write t=ts[0] outputs
    #pragma unroll
    for (int g = 0; g < 2; g++) {
        int P = g ? PB : PA;
        int p0 = 2 * P, p1 = p0 + 1;
        const float4* zr0 = (const float4*)(z0 + (size_t)p0 * 8);
        const float4* zr1 = (const float4*)(z0 + (size_t)p1 * 8);
        float4 a0 = zr0[0], a1 = zr0[1], c0 = zr1[0], c1 = zr1[1];
        u64* z = zz + 8 * g;
        z[0] = pk(a0.x, c0.x); z[1] = pk(a0.y, c0.y);
        z[2] = pk(a0.z, c0.z); z[3] = pk(a0.w, c0.w);
        z[4] = pk(a1.x, c1.x); z[5] = pk(a1.y, c1.y);
        z[6] = pk(a1.z, c1.z); z[7] = pk(a1.w, c1.w);
        float l0 = lp0[p0], l1 = lp0[p1];
        ll[g] = pk(l0, l1);
        float4* o0 = (float4*)(out + (size_t)p0 * 8);
        o0[0] = a0; o0[1] = a1;
        float4* o1 = (float4*)(out + (size_t)p1 * 8);
        o1[0] = c0; o1[1] = c1;
        out[ZT_ELEMS + p0] = l0;
        out[ZT_ELEMS + p1] = l1;
    }

    const u64 two = pk(2.f, 2.f);
    int staged = -1;
    u64 zs[16], dz[16], acc[16], dl[2], lacc[2];

    #pragma unroll 1
    for (int j = 0; j < NSEG; j++) {
        float t0 = ts[j];
        float dt = (ts[j + 1] - t0) * 0.25f;
        u64 dt2 = pk(dt * 0.5f, dt * 0.5f);
        u64 dtf = pk(dt, dt);
        u64 dt6 = pk(dt * (1.f / 6.f), dt * (1.f / 6.f));

        #pragma unroll 1
        for (int s = 0; s < NSUB; s++) {
            int base = j * 9 + 2 * s;
            if (staged != base)
                stage_slot(s4, (const float4*)(g_slots + (size_t)base * SLOT_F), tid);

            // k1
            rhs_eval2(sb, zz, dz, dl);
            #pragma unroll
            for (int d = 0; d < 16; d++) { acc[d] = dz[d]; zs[d] = f2(dt2, dz[d], zz[d]); }
            lacc[0] = dl[0]; lacc[1] = dl[1];

            // k2 (t + dt/2)
            stage_slot(s4, (const float4*)(g_slots + (size_t)(base + 1) * SLOT_F), tid);
            rhs_eval2(sb, zs, dz, dl);
            #pragma unroll
            for (int d = 0; d < 16; d++) { acc[d] = f2(two, dz[d], acc[d]); zs[d] = f2(dt2, dz[d], zz[d]); }
            lacc[0] = f2(two, dl[0], lacc[0]); lacc[1] = f2(two, dl[1], lacc[1]);

            // k3 (same slot, no restage)
            rhs_eval2(sb, zs, dz, dl);
            #pragma unroll
            for (int d = 0; d < 16; d++) { acc[d] = f2(two, dz[d], acc[d]); zs[d] = f2(dtf, dz[d], zz[d]); }
            lacc[0] = f2(two, dl[0], lacc[0]); lacc[1] = f2(two, dl[1], lacc[1]);

            // k4 (t + dt)
            stage_slot(s4, (const float4*)(g_slots + (size_t)(base + 2) * SLOT_F), tid);
            rhs_eval2(sb, zs, dz, dl);
            #pragma unroll
            for (int d = 0; d < 16; d++) { acc[d] = a2(acc[d], dz[d]); zz[d] = f2(dt6, acc[d], zz[d]); }
            lacc[0] = a2(lacc[0], dl[0]); lacc[1] = a2(lacc[1], dl[1]);
            ll[0] = f2(dt6, lacc[0], ll[0]); ll[1] = f2(dt6, lacc[1], ll[1]);

            staged = base + 2;
        }

        // write outputs at time index j+1
        size_t ob = (size_t)(j + 1) * NPART;
        #pragma unroll
        for (int g = 0; g < 2; g++) {
            int P = g ? PB : PA;
            int p0 = 2 * P, p1 = p0 + 1;
            const u64* z = zz + 8 * g;
            float zx[8], zy[8];
            #pragma unroll
            for (int d = 0; d < 8; d++) upk(zx[d], zy[d], z[d]);
            float4* w0p = (float4*)(out + (ob + p0) * 8);
            w0p[0] = make_float4(zx[0], zx[1], zx[2], zx[3]);
            w0p[1] = make_float4(zx[4], zx[5], zx[6], zx[7]);
            float4* w1p = (float4*)(out + (ob + p1) * 8);
            w1p[0] = make_float4(zy[0], zy[1], zy[2], zy[3]);
            w1p[1] = make_float4(zy[4], zy[5], zy[6], zy[7]);
            float lx, lyv; upk(lx, lyv, ll[g]);
            out[ZT_ELEMS + ob + p0] = lx;
            out[ZT_ELEMS + ob + p1] = lyv;
        }
    }
}

// ---------------- launch ----------------
extern "C" void kernel_launch(void* const* d_in, const int* in_sizes, int n_in,
                              void* d_out, int out_size)
{
    const float* ts  = (const float*)d_in[0];
    const float* z0  = (const float*)d_in[1];
    const float* lp0 = (const float*)d_in[2];
    const float* w1  = (const float*)d_in[3];
    const float* b1  = (const float*)d_in[4];
    const float* w2  = (const float*)d_in[5];
    const float* b2  = (const float*)d_in[6];
    const float* w3  = (const float*)d_in[7];
    const float* b3  = (const float*)d_in[8];
    float* out = (float*)d_out;

    hyper_kernel<<<NSLOT, 128>>>(ts, w1, b1, w2, b2, w3, b3);
    cnf_main<<<NPART / 512, 128>>>(ts, z0, lp0, out);
    (void)in_sizes; (void)n_in; (void)out_size;
}